// round 2
// baseline (speedup 1.0000x reference)
#include <cuda_runtime.h>
#include <math.h>

#define L_SEQ 32768
#define H_DIM 512
#define P_DIM 256
#define CHUNK 512
#define NCHUNK (L_SEQ / CHUNK)   // 64

// Scratch planes in [P][L] layout. Bu is written here by gemm1, then
// overwritten in place with the scanned state x by scan_apply.
__device__ float g_x_re[(size_t)P_DIM * L_SEQ];
__device__ float g_x_im[(size_t)P_DIM * L_SEQ];
__device__ float g_agg[P_DIM * NCHUNK * 4];   // per-(p,chunk) aggregate (Ar,Ai,br,bi)
__device__ float g_pre[P_DIM * NCHUNK * 2];   // per-(p,chunk) exclusive prefix b (re,im)

// combine(prev, cur) where prev is EARLIER: result = (Acur*Aprev, Acur*bprev + bcur)
__device__ __forceinline__ void combine_right(float& Ar, float& Ai, float& br, float& bi,
                                              float pAr, float pAi, float pbr, float pbi)
{
    float nAr = Ar*pAr - Ai*pAi;
    float nAi = Ar*pAi + Ai*pAr;
    float nbr = Ar*pbr - Ai*pbi + br;
    float nbi = Ar*pbi + Ai*pbr + bi;
    Ar = nAr; Ai = nAi; br = nbr; bi = nbi;
}

// self is EARLIER (left), received r* is LATER: result = (Aright*Aleft, Aright*bleft + bright)
__device__ __forceinline__ void combine_left(float& Ar, float& Ai, float& br, float& bi,
                                             float rAr, float rAi, float rbr, float rbi)
{
    float nAr = rAr*Ar - rAi*Ai;
    float nAi = rAr*Ai + rAi*Ar;
    float nbr = rAr*br - rAi*bi + rbr;
    float nbi = rAr*bi + rAi*br + rbi;
    Ar = nAr; Ai = nAi; br = nbr; bi = nbi;
}

__device__ __forceinline__ void lambda_bar(float lre, float lim, float Dl, float& Ar, float& Ai)
{
    float e = expf(lre * Dl);
    float s, c;
    sincosf(lim * Dl, &s, &c);
    Ar = e * c;
    Ai = e * s;
}

// ======================== GEMM1: Bu = gamma_bar * (u @ B^T) ========================
// A = u (L x H, row-major, K=H contiguous); B = B_re/B_im (P x H, K contiguous).
// Output written directly to [P][L] planes with the gamma_bar epilogue fused.
#define BM1 128
#define BN1 64
#define BK1 16

__global__ __launch_bounds__(256) void gemm1(
    const float* __restrict__ u, const float* __restrict__ Bre, const float* __restrict__ Bim,
    const float* __restrict__ dtv, const float* __restrict__ Lre_g, const float* __restrict__ Lim_g,
    const float* __restrict__ logstep)
{
    __shared__ float As[BK1][BM1];
    __shared__ float Bsr[BK1][BN1];
    __shared__ float Bsi[BK1][BN1];

    const int bm = blockIdx.y * BM1;  // l offset
    const int bn = blockIdx.x * BN1;  // p offset
    const int tid = threadIdx.x;
    const int ty = tid >> 4;   // 0..15  (rows: 8 l each)
    const int tx = tid & 15;   // 0..15  (cols: 4 p each)

    float accr[8][4] = {};
    float acci[8][4] = {};

    for (int kt = 0; kt < H_DIM; kt += BK1) {
        // A tile: 128 x 16
#pragma unroll
        for (int r = 0; r < 2; r++) {
            int idx = tid + r * 256;
            int row = idx >> 2;
            int c4 = (idx & 3) << 2;
            float4 v = *(const float4*)(u + (size_t)(bm + row) * H_DIM + kt + c4);
            As[c4 + 0][row] = v.x; As[c4 + 1][row] = v.y;
            As[c4 + 2][row] = v.z; As[c4 + 3][row] = v.w;
        }
        // B tiles: 64 x 16 each plane
        {
            int row = tid >> 2;
            int c4 = (tid & 3) << 2;
            float4 vr = *(const float4*)(Bre + (size_t)(bn + row) * H_DIM + kt + c4);
            Bsr[c4 + 0][row] = vr.x; Bsr[c4 + 1][row] = vr.y;
            Bsr[c4 + 2][row] = vr.z; Bsr[c4 + 3][row] = vr.w;
            float4 vi = *(const float4*)(Bim + (size_t)(bn + row) * H_DIM + kt + c4);
            Bsi[c4 + 0][row] = vi.x; Bsi[c4 + 1][row] = vi.y;
            Bsi[c4 + 2][row] = vi.z; Bsi[c4 + 3][row] = vi.w;
        }
        __syncthreads();

#pragma unroll
        for (int k = 0; k < BK1; k++) {
            float a[8], br[4], bi[4];
            *(float4*)&a[0] = *(float4*)&As[k][ty * 8];
            *(float4*)&a[4] = *(float4*)&As[k][ty * 8 + 4];
            *(float4*)&br[0] = *(float4*)&Bsr[k][tx * 4];
            *(float4*)&bi[0] = *(float4*)&Bsi[k][tx * 4];
#pragma unroll
            for (int i = 0; i < 8; i++) {
#pragma unroll
                for (int j = 0; j < 4; j++) {
                    accr[i][j] = fmaf(a[i], br[j], accr[i][j]);
                    acci[i][j] = fmaf(a[i], bi[j], acci[i][j]);
                }
            }
        }
        __syncthreads();
    }

    // Epilogue: multiply by gamma_bar = (Lambda_bar - 1) * conj(Lambda) / |Lambda|^2
    const int l0 = bm + ty * 8;
    float dt[8];
#pragma unroll
    for (int i = 0; i < 8; i++) dt[i] = dtv[l0 + i];

#pragma unroll
    for (int j = 0; j < 4; j++) {
        int p = bn + tx * 4 + j;
        float lre = Lre_g[p], lim = Lim_g[p];
        float stp = expf(logstep[p]);
        float inv = 1.0f / (lre * lre + lim * lim);
        float o_re[8], o_im[8];
#pragma unroll
        for (int i = 0; i < 8; i++) {
            float Dl = dt[i] * stp;
            float Ar, Ai;
            lambda_bar(lre, lim, Dl, Ar, Ai);
            float gr = ((Ar - 1.0f) * lre + Ai * lim) * inv;
            float gi = (Ai * lre - (Ar - 1.0f) * lim) * inv;
            o_re[i] = gr * accr[i][j] - gi * acci[i][j];
            o_im[i] = gr * acci[i][j] + gi * accr[i][j];
        }
        float* pr = g_x_re + (size_t)p * L_SEQ + l0;
        float* pi = g_x_im + (size_t)p * L_SEQ + l0;
        *(float4*)(pr)     = make_float4(o_re[0], o_re[1], o_re[2], o_re[3]);
        *(float4*)(pr + 4) = make_float4(o_re[4], o_re[5], o_re[6], o_re[7]);
        *(float4*)(pi)     = make_float4(o_im[0], o_im[1], o_im[2], o_im[3]);
        *(float4*)(pi + 4) = make_float4(o_im[4], o_im[5], o_im[6], o_im[7]);
    }
}

// ======================== Scan phase A: per-(p,chunk) ordered reduce ========================
__global__ __launch_bounds__(512) void scan_agg(
    const float* __restrict__ dtv, const float* __restrict__ Lre_g,
    const float* __restrict__ Lim_g, const float* __restrict__ logstep)
{
    const int p = blockIdx.y;
    const int chunk = blockIdx.x;
    const int tid = threadIdx.x;
    const int l = chunk * CHUNK + tid;

    float lre = Lre_g[p], lim = Lim_g[p];
    float stp = expf(logstep[p]);
    float Ar, Ai;
    lambda_bar(lre, lim, dtv[l] * stp, Ar, Ai);
    float br = g_x_re[(size_t)p * L_SEQ + l];
    float bi = g_x_im[(size_t)p * L_SEQ + l];

    // ordered warp reduce (adjacent segments): lane 0 ends with warp aggregate
#pragma unroll
    for (int off = 1; off < 32; off <<= 1) {
        float rAr = __shfl_down_sync(0xFFFFFFFFu, Ar, off);
        float rAi = __shfl_down_sync(0xFFFFFFFFu, Ai, off);
        float rbr = __shfl_down_sync(0xFFFFFFFFu, br, off);
        float rbi = __shfl_down_sync(0xFFFFFFFFu, bi, off);
        combine_left(Ar, Ai, br, bi, rAr, rAi, rbr, rbi);
    }

    __shared__ float sA_r[16], sA_i[16], sb_r[16], sb_i[16];
    int lane = tid & 31, wid = tid >> 5;
    if (lane == 0) { sA_r[wid] = Ar; sA_i[wid] = Ai; sb_r[wid] = br; sb_i[wid] = bi; }
    __syncthreads();

    if (wid == 0) {
        float aAr = (lane < 16) ? sA_r[lane] : 1.0f;
        float aAi = (lane < 16) ? sA_i[lane] : 0.0f;
        float abr = (lane < 16) ? sb_r[lane] : 0.0f;
        float abi = (lane < 16) ? sb_i[lane] : 0.0f;
#pragma unroll
        for (int off = 1; off < 16; off <<= 1) {
            float rAr = __shfl_down_sync(0xFFFFFFFFu, aAr, off);
            float rAi = __shfl_down_sync(0xFFFFFFFFu, aAi, off);
            float rbr = __shfl_down_sync(0xFFFFFFFFu, abr, off);
            float rbi = __shfl_down_sync(0xFFFFFFFFu, abi, off);
            combine_left(aAr, aAi, abr, abi, rAr, rAi, rbr, rbi);
        }
        if (lane == 0) {
            size_t o = ((size_t)p * NCHUNK + chunk) * 4;
            g_agg[o + 0] = aAr; g_agg[o + 1] = aAi;
            g_agg[o + 2] = abr; g_agg[o + 3] = abi;
        }
    }
}

// ======================== Scan phase B: per-p scan over chunk aggregates ========================
__global__ __launch_bounds__(64) void chunk_prefix()
{
    const int p = blockIdx.x;
    const int tid = threadIdx.x;  // 64 = NCHUNK
    size_t o = ((size_t)p * NCHUNK + tid) * 4;
    float Ar = g_agg[o + 0], Ai = g_agg[o + 1];
    float br = g_agg[o + 2], bi = g_agg[o + 3];

    int lane = tid & 31, wid = tid >> 5;
#pragma unroll
    for (int off = 1; off < 32; off <<= 1) {
        float pAr = __shfl_up_sync(0xFFFFFFFFu, Ar, off);
        float pAi = __shfl_up_sync(0xFFFFFFFFu, Ai, off);
        float pbr = __shfl_up_sync(0xFFFFFFFFu, br, off);
        float pbi = __shfl_up_sync(0xFFFFFFFFu, bi, off);
        if (lane >= off) combine_right(Ar, Ai, br, bi, pAr, pAi, pbr, pbi);
    }

    __shared__ float w0[4];
    __shared__ float sb[NCHUNK][2];
    if (wid == 0 && lane == 31) { w0[0] = Ar; w0[1] = Ai; w0[2] = br; w0[3] = bi; }
    __syncthreads();
    if (wid == 1) combine_right(Ar, Ai, br, bi, w0[0], w0[1], w0[2], w0[3]);
    sb[tid][0] = br; sb[tid][1] = bi;
    __syncthreads();

    float pr = tid ? sb[tid - 1][0] : 0.0f;
    float pi = tid ? sb[tid - 1][1] : 0.0f;
    size_t q = ((size_t)p * NCHUNK + tid) * 2;
    g_pre[q] = pr; g_pre[q + 1] = pi;
}

// ======================== Scan phase C: block inclusive scan + apply prefix ========================
__global__ __launch_bounds__(512) void scan_apply(
    const float* __restrict__ dtv, const float* __restrict__ Lre_g,
    const float* __restrict__ Lim_g, const float* __restrict__ logstep)
{
    const int p = blockIdx.y;
    const int chunk = blockIdx.x;
    const int tid = threadIdx.x;
    const int l = chunk * CHUNK + tid;

    float lre = Lre_g[p], lim = Lim_g[p];
    float stp = expf(logstep[p]);
    float Ar, Ai;
    lambda_bar(lre, lim, dtv[l] * stp, Ar, Ai);
    float br = g_x_re[(size_t)p * L_SEQ + l];
    float bi = g_x_im[(size_t)p * L_SEQ + l];

    int lane = tid & 31, wid = tid >> 5;
    // warp inclusive scan
#pragma unroll
    for (int off = 1; off < 32; off <<= 1) {
        float pAr = __shfl_up_sync(0xFFFFFFFFu, Ar, off);
        float pAi = __shfl_up_sync(0xFFFFFFFFu, Ai, off);
        float pbr = __shfl_up_sync(0xFFFFFFFFu, br, off);
        float pbi = __shfl_up_sync(0xFFFFFFFFu, bi, off);
        if (lane >= off) combine_right(Ar, Ai, br, bi, pAr, pAi, pbr, pbi);
    }

    __shared__ float sA_r[16], sA_i[16], sb_r[16], sb_i[16];
    if (lane == 31) { sA_r[wid] = Ar; sA_i[wid] = Ai; sb_r[wid] = br; sb_i[wid] = bi; }
    __syncthreads();

    if (wid == 0) {
        float aAr = (lane < 16) ? sA_r[lane] : 1.0f;
        float aAi = (lane < 16) ? sA_i[lane] : 0.0f;
        float abr = (lane < 16) ? sb_r[lane] : 0.0f;
        float abi = (lane < 16) ? sb_i[lane] : 0.0f;
#pragma unroll
        for (int off = 1; off < 16; off <<= 1) {
            float pAr = __shfl_up_sync(0xFFFFFFFFu, aAr, off);
            float pAi = __shfl_up_sync(0xFFFFFFFFu, aAi, off);
            float pbr = __shfl_up_sync(0xFFFFFFFFu, abr, off);
            float pbi = __shfl_up_sync(0xFFFFFFFFu, abi, off);
            if (lane >= off && lane < 16) combine_right(aAr, aAi, abr, abi, pAr, pAi, pbr, pbi);
        }
        if (lane < 16) { sA_r[lane] = aAr; sA_i[lane] = aAi; sb_r[lane] = abr; sb_i[lane] = abi; }
    }
    __syncthreads();

    if (wid > 0)
        combine_right(Ar, Ai, br, bi, sA_r[wid - 1], sA_i[wid - 1], sb_r[wid - 1], sb_i[wid - 1]);

    // apply cross-chunk prefix: x = A_local * b_prefix + b_local
    size_t q = ((size_t)p * NCHUNK + chunk) * 2;
    float pr = g_pre[q], pi = g_pre[q + 1];
    float xr = Ar * pr - Ai * pi + br;
    float xi = Ar * pi + Ai * pr + bi;
    g_x_re[(size_t)p * L_SEQ + l] = xr;
    g_x_im[(size_t)p * L_SEQ + l] = xi;
}

// ======================== GEMM2: y = 2*(x_re C_re^T - x_im C_im^T) + D*u ========================
// A = x planes in [P][L] (M-major), B = C_re/C_im (H x P, K contiguous).
#define BM2 128
#define BN2 64
#define BK2 16

__global__ __launch_bounds__(256) void gemm2(
    const float* __restrict__ Cre, const float* __restrict__ Cim,
    const float* __restrict__ u, const float* __restrict__ Dg,
    float* __restrict__ out)
{
    __shared__ float Ar_s[BK2][BM2];
    __shared__ float Ai_s[BK2][BM2];
    __shared__ float Br_s[BK2][BN2];
    __shared__ float Bi_s[BK2][BN2];

    const int bm = blockIdx.y * BM2;  // l offset
    const int bn = blockIdx.x * BN2;  // h offset
    const int tid = threadIdx.x;
    const int ty = tid >> 4;
    const int tx = tid & 15;

    float acc[8][4] = {};

    for (int kt = 0; kt < P_DIM; kt += BK2) {
        // A tiles: 16 cols (p) x 128 rows (l), contiguous along l
#pragma unroll
        for (int r = 0; r < 2; r++) {
            int idx = tid + r * 256;
            int col = idx >> 5;          // 0..15
            int r4 = (idx & 31) << 2;    // 0..124
            *(float4*)&Ar_s[col][r4] = *(const float4*)(g_x_re + (size_t)(kt + col) * L_SEQ + bm + r4);
            *(float4*)&Ai_s[col][r4] = *(const float4*)(g_x_im + (size_t)(kt + col) * L_SEQ + bm + r4);
        }
        // B tiles: 64 rows (h) x 16 (p)
        {
            int row = tid >> 2;
            int c4 = (tid & 3) << 2;
            float4 vr = *(const float4*)(Cre + (size_t)(bn + row) * P_DIM + kt + c4);
            Br_s[c4 + 0][row] = vr.x; Br_s[c4 + 1][row] = vr.y;
            Br_s[c4 + 2][row] = vr.z; Br_s[c4 + 3][row] = vr.w;
            float4 vi = *(const float4*)(Cim + (size_t)(bn + row) * P_DIM + kt + c4);
            Bi_s[c4 + 0][row] = vi.x; Bi_s[c4 + 1][row] = vi.y;
            Bi_s[c4 + 2][row] = vi.z; Bi_s[c4 + 3][row] = vi.w;
        }
        __syncthreads();

#pragma unroll
        for (int k = 0; k < BK2; k++) {
            float ar[8], ai[8], br[4], bi[4];
            *(float4*)&ar[0] = *(float4*)&Ar_s[k][ty * 8];
            *(float4*)&ar[4] = *(float4*)&Ar_s[k][ty * 8 + 4];
            *(float4*)&ai[0] = *(float4*)&Ai_s[k][ty * 8];
            *(float4*)&ai[4] = *(float4*)&Ai_s[k][ty * 8 + 4];
            *(float4*)&br[0] = *(float4*)&Br_s[k][tx * 4];
            *(float4*)&bi[0] = *(float4*)&Bi_s[k][tx * 4];
#pragma unroll
            for (int i = 0; i < 8; i++) {
#pragma unroll
                for (int j = 0; j < 4; j++) {
                    acc[i][j] = fmaf(ar[i], br[j], acc[i][j]);
                    acc[i][j] = fmaf(-ai[i], bi[j], acc[i][j]);
                }
            }
        }
        __syncthreads();
    }

    // Epilogue: y = 2*acc + D*u
    const int l0 = bm + ty * 8;
    const int h0 = bn + tx * 4;
    float4 dd = *(const float4*)(Dg + h0);
#pragma unroll
    for (int i = 0; i < 8; i++) {
        float4 uu = *(const float4*)(u + (size_t)(l0 + i) * H_DIM + h0);
        float4 o;
        o.x = 2.0f * acc[i][0] + dd.x * uu.x;
        o.y = 2.0f * acc[i][1] + dd.y * uu.y;
        o.z = 2.0f * acc[i][2] + dd.z * uu.z;
        o.w = 2.0f * acc[i][3] + dd.w * uu.w;
        *(float4*)(out + (size_t)(l0 + i) * H_DIM + h0) = o;
    }
}

// ======================== launch ========================
extern "C" void kernel_launch(void* const* d_in, const int* in_sizes, int n_in,
                              void* d_out, int out_size)
{
    const float* u   = (const float*)d_in[0];  // (L, H)
    const float* dtv = (const float*)d_in[1];  // (L,)
    const float* Lre = (const float*)d_in[2];  // (P,)
    const float* Lim = (const float*)d_in[3];  // (P,)
    const float* Bre = (const float*)d_in[4];  // (P, H)
    const float* Bim = (const float*)d_in[5];  // (P, H)
    const float* Cre = (const float*)d_in[6];  // (H, P)
    const float* Cim = (const float*)d_in[7];  // (H, P)
    const float* Dg  = (const float*)d_in[8];  // (H,)
    const float* lst = (const float*)d_in[9];  // (P,)
    float* out = (float*)d_out;                // (L, H)

    gemm1<<<dim3(P_DIM / BN1, L_SEQ / BM1), 256>>>(u, Bre, Bim, dtv, Lre, Lim, lst);
    scan_agg<<<dim3(NCHUNK, P_DIM), 512>>>(dtv, Lre, Lim, lst);
    chunk_prefix<<<P_DIM, 64>>>();
    scan_apply<<<dim3(NCHUNK, P_DIM), 512>>>(dtv, Lre, Lim, lst);
    gemm2<<<dim3(H_DIM / BN2, L_SEQ / BM2), 256>>>(Cre, Cim, u, Dg, out);
}

// round 5
// speedup vs baseline: 1.4722x; 1.4722x over previous
#include <cuda_runtime.h>
#include <math.h>
#include <stdint.h>

#define L_SEQ 32768
#define H_DIM 512
#define P_DIM 256
#define CHUNK 512
#define NCHUNK (L_SEQ / CHUNK)   // 64

// Scratch planes in [P][L] layout. Bu written by gemm1, overwritten in place
// with the scanned state x by scan_apply, consumed by gemm2.
__device__ float g_x_re[(size_t)P_DIM * L_SEQ];
__device__ float g_x_im[(size_t)P_DIM * L_SEQ];
__device__ float g_agg[P_DIM * NCHUNK * 4];
__device__ float g_pre[P_DIM * NCHUNK * 2];

// ---------------- common helpers ----------------

__device__ __forceinline__ void combine_right(float& Ar, float& Ai, float& br, float& bi,
                                              float pAr, float pAi, float pbr, float pbi)
{
    float nAr = Ar*pAr - Ai*pAi;
    float nAi = Ar*pAi + Ai*pAr;
    float nbr = Ar*pbr - Ai*pbi + br;
    float nbi = Ar*pbi + Ai*pbr + bi;
    Ar = nAr; Ai = nAi; br = nbr; bi = nbi;
}

__device__ __forceinline__ void combine_left(float& Ar, float& Ai, float& br, float& bi,
                                             float rAr, float rAi, float rbr, float rbi)
{
    float nAr = rAr*Ar - rAi*Ai;
    float nAi = rAr*Ai + rAi*Ar;
    float nbr = rAr*br - rAi*bi + rbr;
    float nbi = rAr*bi + rAi*br + rbi;
    Ar = nAr; Ai = nAi; br = nbr; bi = nbi;
}

__device__ __forceinline__ void lambda_bar(float lre, float lim, float Dl, float& Ar, float& Ai)
{
    float e = expf(lre * Dl);
    float s, c;
    sincosf(lim * Dl, &s, &c);
    Ar = e * c;
    Ai = e * s;
}

__device__ __forceinline__ uint32_t f2tf32(float x)
{
    uint32_t r;
    asm("cvt.rna.tf32.f32 %0, %1;" : "=r"(r) : "f"(x));
    return r;
}

__device__ __forceinline__ void mma_tf32(float* d, const uint32_t* a, uint32_t b0, uint32_t b1)
{
    asm volatile(
        "mma.sync.aligned.m16n8k8.row.col.f32.tf32.tf32.f32 "
        "{%0,%1,%2,%3}, {%4,%5,%6,%7}, {%8,%9}, {%0,%1,%2,%3};"
        : "+f"(d[0]), "+f"(d[1]), "+f"(d[2]), "+f"(d[3])
        : "r"(a[0]), "r"(a[1]), "r"(a[2]), "r"(a[3]), "r"(b0), "r"(b1));
}

// k-permutation within an 8-group: [k0,k4,k1,k5,k2,k6,k3,k7]
// pos(k) = k<4 ? 2k : 2(k-4)+1  -> LDS.64 at pos 2t yields (k=t, k=t+4)
__device__ __forceinline__ int kperm(int k7) { return (k7 < 4) ? (2 * k7) : (2 * (k7 - 4) + 1); }

// ======================== GEMM1 (tf32 mma): Bu = gamma_bar * (u @ B^T) ========================
// D[l, p] = sum_h u[l,h] * B[p,h].  A = u (row l, k h) "row"; B = Bre/Bim (n p, k h) -> "col".
#define G1_BM 128
#define G1_BN 128
#define G1_BK 32
#define G1_AK8 (G1_BM * 8 + 8)   // 1032 floats per k8 plane (pad 8 for bank spread)
#define G1_BK8 (G1_BN * 8 + 8)   // 1032
#define G1_A_OFF 0
#define G1_BR_OFF (4 * G1_AK8)                 // 4128
#define G1_BI_OFF (G1_BR_OFF + 4 * G1_BK8)     // 8256
#define G1_SMEM_FLOATS (G1_BI_OFF + 4 * G1_BK8)  // 12384 -> 49536 B
#define G1_SMEM_BYTES (G1_SMEM_FLOATS * 4)

__global__ __launch_bounds__(512, 1) void gemm1(
    const float* __restrict__ u, const float* __restrict__ Bre, const float* __restrict__ Bim,
    const float* __restrict__ dtv, const float* __restrict__ Lre_g, const float* __restrict__ Lim_g,
    const float* __restrict__ logstep)
{
    extern __shared__ uint32_t sm1[];
    const int tid = threadIdx.x;
    const int wid = tid >> 5, lane = tid & 31;
    const int g = lane >> 2, t = lane & 3;
    const int wm = wid >> 2, wn = wid & 3;           // 4 x 4 warp grid, warp tile 32l x 32p
    const int bm = blockIdx.y * G1_BM;
    const int bn = blockIdx.x * G1_BN;

    float accr[2][4][4];
    float acci[2][4][4];
#pragma unroll
    for (int i = 0; i < 2; i++)
#pragma unroll
        for (int j = 0; j < 4; j++)
#pragma unroll
            for (int r = 0; r < 4; r++) { accr[i][j][r] = 0.0f; acci[i][j][r] = 0.0f; }

    for (int kt = 0; kt < H_DIM; kt += G1_BK) {
        // fill A (u): 128 rows x 32 k
#pragma unroll
        for (int r = 0; r < 2; r++) {
            int idx = tid + r * 512;
            int row = idx >> 3, k4 = idx & 7;
            float4 v = *(const float4*)(u + (size_t)(bm + row) * H_DIM + kt + k4 * 4);
            int base = G1_A_OFF + (k4 >> 1) * G1_AK8 + row * 8 + (k4 & 1);
            sm1[base + 0] = f2tf32(v.x); sm1[base + 2] = f2tf32(v.y);
            sm1[base + 4] = f2tf32(v.z); sm1[base + 6] = f2tf32(v.w);
        }
        // fill Bre / Bim: 128 rows (p) x 32 k
#pragma unroll
        for (int r = 0; r < 2; r++) {
            int idx = tid + r * 512;
            int row = idx >> 3, k4 = idx & 7;
            int off = (k4 >> 1) * G1_BK8 + row * 8 + (k4 & 1);
            float4 vr = *(const float4*)(Bre + (size_t)(bn + row) * H_DIM + kt + k4 * 4);
            sm1[G1_BR_OFF + off + 0] = f2tf32(vr.x); sm1[G1_BR_OFF + off + 2] = f2tf32(vr.y);
            sm1[G1_BR_OFF + off + 4] = f2tf32(vr.z); sm1[G1_BR_OFF + off + 6] = f2tf32(vr.w);
            float4 vi = *(const float4*)(Bim + (size_t)(bn + row) * H_DIM + kt + k4 * 4);
            sm1[G1_BI_OFF + off + 0] = f2tf32(vi.x); sm1[G1_BI_OFF + off + 2] = f2tf32(vi.y);
            sm1[G1_BI_OFF + off + 4] = f2tf32(vi.z); sm1[G1_BI_OFF + off + 6] = f2tf32(vi.w);
        }
        __syncthreads();

#pragma unroll
        for (int k8 = 0; k8 < 4; k8++) {
            uint32_t a[2][4];
#pragma unroll
            for (int mt = 0; mt < 2; mt++) {
                int row = wm * 32 + mt * 16 + g;
                const uint32_t* p0 = &sm1[G1_A_OFF + k8 * G1_AK8 + row * 8 + 2 * t];
                uint2 lo = *(const uint2*)p0;
                uint2 hi = *(const uint2*)(p0 + 64);   // row + 8
                a[mt][0] = lo.x; a[mt][2] = lo.y;
                a[mt][1] = hi.x; a[mt][3] = hi.y;
            }
#pragma unroll
            for (int nt = 0; nt < 4; nt++) {
                int row = wn * 32 + nt * 8 + g;
                uint2 br = *(const uint2*)&sm1[G1_BR_OFF + k8 * G1_BK8 + row * 8 + 2 * t];
                uint2 bi = *(const uint2*)&sm1[G1_BI_OFF + k8 * G1_BK8 + row * 8 + 2 * t];
#pragma unroll
                for (int mt = 0; mt < 2; mt++) {
                    mma_tf32(accr[mt][nt], a[mt], br.x, br.y);
                    mma_tf32(acci[mt][nt], a[mt], bi.x, bi.y);
                }
            }
        }
        __syncthreads();
    }

    // epilogue: gamma_bar multiply, store to [P][L] planes
    float dts[2][2];
#pragma unroll
    for (int mt = 0; mt < 2; mt++)
#pragma unroll
        for (int rh = 0; rh < 2; rh++)
            dts[mt][rh] = dtv[bm + wm * 32 + mt * 16 + g + rh * 8];

#pragma unroll
    for (int nt = 0; nt < 4; nt++) {
#pragma unroll
        for (int c = 0; c < 2; c++) {
            int p = bn + wn * 32 + nt * 8 + 2 * t + c;
            float lre = Lre_g[p], lim = Lim_g[p];
            float stp = expf(logstep[p]);
            float inv = 1.0f / (lre * lre + lim * lim);
#pragma unroll
            for (int mt = 0; mt < 2; mt++) {
#pragma unroll
                for (int rh = 0; rh < 2; rh++) {
                    int l = bm + wm * 32 + mt * 16 + g + rh * 8;
                    float Dl = dts[mt][rh] * stp;
                    float Ar, Ai;
                    lambda_bar(lre, lim, Dl, Ar, Ai);
                    float gr = ((Ar - 1.0f) * lre + Ai * lim) * inv;
                    float gi = (Ai * lre - (Ar - 1.0f) * lim) * inv;
                    int reg = rh * 2 + c;
                    float ar = accr[mt][nt][reg], ai = acci[mt][nt][reg];
                    size_t o = (size_t)p * L_SEQ + l;
                    g_x_re[o] = gr * ar - gi * ai;
                    g_x_im[o] = gr * ai + gi * ar;
                }
            }
        }
    }
}

// ======================== Scan phase A ========================
__global__ __launch_bounds__(512) void scan_agg(
    const float* __restrict__ dtv, const float* __restrict__ Lre_g,
    const float* __restrict__ Lim_g, const float* __restrict__ logstep)
{
    const int p = blockIdx.y;
    const int chunk = blockIdx.x;
    const int tid = threadIdx.x;
    const int l = chunk * CHUNK + tid;

    float lre = Lre_g[p], lim = Lim_g[p];
    float stp = expf(logstep[p]);
    float Ar, Ai;
    lambda_bar(lre, lim, dtv[l] * stp, Ar, Ai);
    float br = g_x_re[(size_t)p * L_SEQ + l];
    float bi = g_x_im[(size_t)p * L_SEQ + l];

#pragma unroll
    for (int off = 1; off < 32; off <<= 1) {
        float rAr = __shfl_down_sync(0xFFFFFFFFu, Ar, off);
        float rAi = __shfl_down_sync(0xFFFFFFFFu, Ai, off);
        float rbr = __shfl_down_sync(0xFFFFFFFFu, br, off);
        float rbi = __shfl_down_sync(0xFFFFFFFFu, bi, off);
        combine_left(Ar, Ai, br, bi, rAr, rAi, rbr, rbi);
    }

    __shared__ float sA_r[16], sA_i[16], sb_r[16], sb_i[16];
    int lane = tid & 31, wid = tid >> 5;
    if (lane == 0) { sA_r[wid] = Ar; sA_i[wid] = Ai; sb_r[wid] = br; sb_i[wid] = bi; }
    __syncthreads();

    if (wid == 0) {
        float aAr = (lane < 16) ? sA_r[lane] : 1.0f;
        float aAi = (lane < 16) ? sA_i[lane] : 0.0f;
        float abr = (lane < 16) ? sb_r[lane] : 0.0f;
        float abi = (lane < 16) ? sb_i[lane] : 0.0f;
#pragma unroll
        for (int off = 1; off < 16; off <<= 1) {
            float rAr = __shfl_down_sync(0xFFFFFFFFu, aAr, off);
            float rAi = __shfl_down_sync(0xFFFFFFFFu, aAi, off);
            float rbr = __shfl_down_sync(0xFFFFFFFFu, abr, off);
            float rbi = __shfl_down_sync(0xFFFFFFFFu, abi, off);
            combine_left(aAr, aAi, abr, abi, rAr, rAi, rbr, rbi);
        }
        if (lane == 0) {
            size_t o = ((size_t)p * NCHUNK + chunk) * 4;
            g_agg[o + 0] = aAr; g_agg[o + 1] = aAi;
            g_agg[o + 2] = abr; g_agg[o + 3] = abi;
        }
    }
}

// ======================== Scan phase B ========================
__global__ __launch_bounds__(64) void chunk_prefix()
{
    const int p = blockIdx.x;
    const int tid = threadIdx.x;
    size_t o = ((size_t)p * NCHUNK + tid) * 4;
    float Ar = g_agg[o + 0], Ai = g_agg[o + 1];
    float br = g_agg[o + 2], bi = g_agg[o + 3];

    int lane = tid & 31, wid = tid >> 5;
#pragma unroll
    for (int off = 1; off < 32; off <<= 1) {
        float pAr = __shfl_up_sync(0xFFFFFFFFu, Ar, off);
        float pAi = __shfl_up_sync(0xFFFFFFFFu, Ai, off);
        float pbr = __shfl_up_sync(0xFFFFFFFFu, br, off);
        float pbi = __shfl_up_sync(0xFFFFFFFFu, bi, off);
        if (lane >= off) combine_right(Ar, Ai, br, bi, pAr, pAi, pbr, pbi);
    }

    __shared__ float w0[4];
    __shared__ float sb[NCHUNK][2];
    if (wid == 0 && lane == 31) { w0[0] = Ar; w0[1] = Ai; w0[2] = br; w0[3] = bi; }
    __syncthreads();
    if (wid == 1) combine_right(Ar, Ai, br, bi, w0[0], w0[1], w0[2], w0[3]);
    sb[tid][0] = br; sb[tid][1] = bi;
    __syncthreads();

    float pr = tid ? sb[tid - 1][0] : 0.0f;
    float pi = tid ? sb[tid - 1][1] : 0.0f;
    size_t q = ((size_t)p * NCHUNK + tid) * 2;
    g_pre[q] = pr; g_pre[q + 1] = pi;
}

// ======================== Scan phase C ========================
__global__ __launch_bounds__(512) void scan_apply(
    const float* __restrict__ dtv, const float* __restrict__ Lre_g,
    const float* __restrict__ Lim_g, const float* __restrict__ logstep)
{
    const int p = blockIdx.y;
    const int chunk = blockIdx.x;
    const int tid = threadIdx.x;
    const int l = chunk * CHUNK + tid;

    float lre = Lre_g[p], lim = Lim_g[p];
    float stp = expf(logstep[p]);
    float Ar, Ai;
    lambda_bar(lre, lim, dtv[l] * stp, Ar, Ai);
    float br = g_x_re[(size_t)p * L_SEQ + l];
    float bi = g_x_im[(size_t)p * L_SEQ + l];

    int lane = tid & 31, wid = tid >> 5;
#pragma unroll
    for (int off = 1; off < 32; off <<= 1) {
        float pAr = __shfl_up_sync(0xFFFFFFFFu, Ar, off);
        float pAi = __shfl_up_sync(0xFFFFFFFFu, Ai, off);
        float pbr = __shfl_up_sync(0xFFFFFFFFu, br, off);
        float pbi = __shfl_up_sync(0xFFFFFFFFu, bi, off);
        if (lane >= off) combine_right(Ar, Ai, br, bi, pAr, pAi, pbr, pbi);
    }

    __shared__ float sA_r[16], sA_i[16], sb_r[16], sb_i[16];
    if (lane == 31) { sA_r[wid] = Ar; sA_i[wid] = Ai; sb_r[wid] = br; sb_i[wid] = bi; }
    __syncthreads();

    if (wid == 0) {
        float aAr = (lane < 16) ? sA_r[lane] : 1.0f;
        float aAi = (lane < 16) ? sA_i[lane] : 0.0f;
        float abr = (lane < 16) ? sb_r[lane] : 0.0f;
        float abi = (lane < 16) ? sb_i[lane] : 0.0f;
#pragma unroll
        for (int off = 1; off < 16; off <<= 1) {
            float pAr = __shfl_up_sync(0xFFFFFFFFu, aAr, off);
            float pAi = __shfl_up_sync(0xFFFFFFFFu, aAi, off);
            float pbr = __shfl_up_sync(0xFFFFFFFFu, abr, off);
            float pbi = __shfl_up_sync(0xFFFFFFFFu, abi, off);
            if (lane >= off && lane < 16) combine_right(aAr, aAi, abr, abi, pAr, pAi, pbr, pbi);
        }
        if (lane < 16) { sA_r[lane] = aAr; sA_i[lane] = aAi; sb_r[lane] = abr; sb_i[lane] = abi; }
    }
    __syncthreads();

    if (wid > 0)
        combine_right(Ar, Ai, br, bi, sA_r[wid - 1], sA_i[wid - 1], sb_r[wid - 1], sb_i[wid - 1]);

    size_t q = ((size_t)p * NCHUNK + chunk) * 2;
    float pr = g_pre[q], pi = g_pre[q + 1];
    float xr = Ar * pr - Ai * pi + br;
    float xi = Ar * pi + Ai * pr + bi;
    g_x_re[(size_t)p * L_SEQ + l] = xr;
    g_x_im[(size_t)p * L_SEQ + l] = xi;
}

// ======================== GEMM2 (tf32 mma): y = 2*(xre Cre^T - xim Cim^T) + D*u ========================
// D[l, h] = sum_p xre[p,l]*Cre[h,p] + (-xim[p,l])*Cim[h,p].  BN=512 => x streamed from DRAM once.
#define G2_BM 64
#define G2_BN 512
#define G2_BK 32
#define G2_AK8 (G2_BM * 8 + 8)    // 520
#define G2_BK8 (G2_BN * 8 + 8)    // 4104
#define G2_AR_OFF 0
#define G2_AI_OFF (4 * G2_AK8)                   // 2080
#define G2_BR_OFF (2 * 4 * G2_AK8)               // 4160
#define G2_BI_OFF (G2_BR_OFF + 4 * G2_BK8)       // 20576
#define G2_SMEM_FLOATS (G2_BI_OFF + 4 * G2_BK8)  // 36992 -> 147968 B
#define G2_SMEM_BYTES (G2_SMEM_FLOATS * 4)

__global__ __launch_bounds__(512, 1) void gemm2(
    const float* __restrict__ Cre, const float* __restrict__ Cim,
    const float* __restrict__ u, const float* __restrict__ Dg,
    float* __restrict__ out)
{
    extern __shared__ uint32_t sm2[];
    const int tid = threadIdx.x;
    const int wid = tid >> 5, lane = tid & 31;
    const int g = lane >> 2, t = lane & 3;
    const int wm = wid >> 3, wn = wid & 7;        // 2 x 8 warp grid, warp tile 32l x 64h
    const int bm = blockIdx.x * G2_BM;

    float acc[2][8][4];
#pragma unroll
    for (int i = 0; i < 2; i++)
#pragma unroll
        for (int j = 0; j < 8; j++)
#pragma unroll
            for (int r = 0; r < 4; r++) acc[i][j][r] = 0.0f;

    for (int kt = 0; kt < P_DIM; kt += G2_BK) {
        // fill A planes (x): k = p-local, rows l. im-plane negated here.
        {
            int k = tid & 31;
            int l4 = (tid >> 5) * 4;
            int k8 = k >> 3, pos = kperm(k & 7);
            float4 vr = *(const float4*)(g_x_re + (size_t)(kt + k) * L_SEQ + bm + l4);
            float4 vi = *(const float4*)(g_x_im + (size_t)(kt + k) * L_SEQ + bm + l4);
            int br_ = G2_AR_OFF + k8 * G2_AK8 + l4 * 8 + pos;
            int bi_ = G2_AI_OFF + k8 * G2_AK8 + l4 * 8 + pos;
            sm2[br_ + 0]  = f2tf32(vr.x); sm2[br_ + 8]  = f2tf32(vr.y);
            sm2[br_ + 16] = f2tf32(vr.z); sm2[br_ + 24] = f2tf32(vr.w);
            sm2[bi_ + 0]  = f2tf32(-vi.x); sm2[bi_ + 8]  = f2tf32(-vi.y);
            sm2[bi_ + 16] = f2tf32(-vi.z); sm2[bi_ + 24] = f2tf32(-vi.w);
        }
        // fill B planes (C): 512 rows (h) x 32 k
#pragma unroll
        for (int j = 0; j < 8; j++) {
            int idx = tid + j * 512;
            int row = idx >> 3, k4 = idx & 7;
            int off = (k4 >> 1) * G2_BK8 + row * 8 + (k4 & 1);
            float4 vr = *(const float4*)(Cre + (size_t)row * P_DIM + kt + k4 * 4);
            sm2[G2_BR_OFF + off + 0] = f2tf32(vr.x); sm2[G2_BR_OFF + off + 2] = f2tf32(vr.y);
            sm2[G2_BR_OFF + off + 4] = f2tf32(vr.z); sm2[G2_BR_OFF + off + 6] = f2tf32(vr.w);
            float4 vi = *(const float4*)(Cim + (size_t)row * P_DIM + kt + k4 * 4);
            sm2[G2_BI_OFF + off + 0] = f2tf32(vi.x); sm2[G2_BI_OFF + off + 2] = f2tf32(vi.y);
            sm2[G2_BI_OFF + off + 4] = f2tf32(vi.z); sm2[G2_BI_OFF + off + 6] = f2tf32(vi.w);
        }
        __syncthreads();

#pragma unroll
        for (int k8 = 0; k8 < 4; k8++) {
            uint32_t ar[2][4], ai[2][4];
#pragma unroll
            for (int mt = 0; mt < 2; mt++) {
                int row = wm * 32 + mt * 16 + g;
                const uint32_t* pr = &sm2[G2_AR_OFF + k8 * G2_AK8 + row * 8 + 2 * t];
                uint2 lo = *(const uint2*)pr;
                uint2 hi = *(const uint2*)(pr + 64);
                ar[mt][0] = lo.x; ar[mt][2] = lo.y; ar[mt][1] = hi.x; ar[mt][3] = hi.y;
                const uint32_t* pi = &sm2[G2_AI_OFF + k8 * G2_AK8 + row * 8 + 2 * t];
                uint2 lo2 = *(const uint2*)pi;
                uint2 hi2 = *(const uint2*)(pi + 64);
                ai[mt][0] = lo2.x; ai[mt][2] = lo2.y; ai[mt][1] = hi2.x; ai[mt][3] = hi2.y;
            }
#pragma unroll
            for (int nt = 0; nt < 8; nt++) {
                int row = wn * 64 + nt * 8 + g;
                uint2 br = *(const uint2*)&sm2[G2_BR_OFF + k8 * G2_BK8 + row * 8 + 2 * t];
                uint2 bi = *(const uint2*)&sm2[G2_BI_OFF + k8 * G2_BK8 + row * 8 + 2 * t];
#pragma unroll
                for (int mt = 0; mt < 2; mt++) {
                    mma_tf32(acc[mt][nt], ar[mt], br.x, br.y);
                    mma_tf32(acc[mt][nt], ai[mt], bi.x, bi.y);
                }
            }
        }
        __syncthreads();
    }

    // epilogue: y = 2*acc + D*u
#pragma unroll
    for (int mt = 0; mt < 2; mt++) {
#pragma unroll
        for (int rh = 0; rh < 2; rh++) {
            int l = bm + wm * 32 + mt * 16 + g + rh * 8;
#pragma unroll
            for (int nt = 0; nt < 8; nt++) {
                int h0 = wn * 64 + nt * 8 + 2 * t;
                float2 uu = *(const float2*)(u + (size_t)l * H_DIM + h0);
                float2 dd = *(const float2*)(Dg + h0);
                float2 o;
                o.x = 2.0f * acc[mt][nt][rh * 2 + 0] + dd.x * uu.x;
                o.y = 2.0f * acc[mt][nt][rh * 2 + 1] + dd.y * uu.y;
                *(float2*)(out + (size_t)l * H_DIM + h0) = o;
            }
        }
    }
}

// ======================== launch ========================
extern "C" void kernel_launch(void* const* d_in, const int* in_sizes, int n_in,
                              void* d_out, int out_size)
{
    const float* u   = (const float*)d_in[0];  // (L, H)
    const float* dtv = (const float*)d_in[1];  // (L,)
    const float* Lre = (const float*)d_in[2];  // (P,)
    const float* Lim = (const float*)d_in[3];  // (P,)
    const float* Bre = (const float*)d_in[4];  // (P, H)
    const float* Bim = (const float*)d_in[5];  // (P, H)
    const float* Cre = (const float*)d_in[6];  // (H, P)
    const float* Cim = (const float*)d_in[7];  // (H, P)
    const float* Dg  = (const float*)d_in[8];  // (H,)
    const float* lst = (const float*)d_in[9];  // (P,)
    float* out = (float*)d_out;                // (L, H)

    static int attr_done = 0;
    if (!attr_done) {
        cudaFuncSetAttribute(gemm1, cudaFuncAttributeMaxDynamicSharedMemorySize, G1_SMEM_BYTES);
        cudaFuncSetAttribute(gemm2, cudaFuncAttributeMaxDynamicSharedMemorySize, G2_SMEM_BYTES);
        attr_done = 1;
    }

    gemm1<<<dim3(P_DIM / G1_BN, L_SEQ / G1_BM), 512, G1_SMEM_BYTES>>>(u, Bre, Bim, dtv, Lre, Lim, lst);
    scan_agg<<<dim3(NCHUNK, P_DIM), 512>>>(dtv, Lre, Lim, lst);
    chunk_prefix<<<P_DIM, 64>>>();
    scan_apply<<<dim3(NCHUNK, P_DIM), 512>>>(dtv, Lre, Lim, lst);
    gemm2<<<L_SEQ / G2_BM, 512, G2_SMEM_BYTES>>>(Cre, Cim, u, Dg, out);
}